// round 16
// baseline (speedup 1.0000x reference)
#include <cuda_runtime.h>
#include <cuda_fp16.h>
#include <cstdint>

#define ROWS 65536
#define H 256
#define IN_SHAPE 512
#define NA 32
#define NACT 16
#define G3 768   // 3*H

// ---------------- scratch (allocation-free: __device__ globals) -------------
__device__ __half g_x [(size_t)ROWS * H];
__device__ __half g_gi[(size_t)ROWS * G3];
__device__ __half g_gh[(size_t)ROWS * G3];
__device__ __half g_h0[(size_t)ROWS * H];
__device__ __half g_h1[(size_t)ROWS * H];
__device__ __half g_c [(size_t)ROWS * H];
__device__ float g_nb[(size_t)ROWS * NA];
__device__ float g_invn[(size_t)ROWS];
// fp16 weights (converted once per launch)
__device__ __half g_hW1  [H * IN_SHAPE];
__device__ __half g_hrWih[G3 * H];
__device__ __half g_hrWhh[G3 * H];
__device__ __half g_hcWih[G3 * H];
__device__ __half g_hcWhh[G3 * H];

__device__ __forceinline__ float sigm(float x) { return 1.0f / (1.0f + __expf(-x)); }
__device__ __forceinline__ float tanh_fast(float x) {
    return 2.0f / (1.0f + __expf(-2.0f * x)) - 1.0f;
}
__device__ __forceinline__ uint32_t h2pack(float lo, float hi) {
    __half2 h = __floats2half2_rn(lo, hi);
    return *(uint32_t*)&h;
}
__device__ __forceinline__ void lds64(uint32_t& a, uint32_t& b, uint32_t addr) {
    asm volatile("ld.shared.v2.b32 {%0,%1}, [%2];"
                 : "=r"(a), "=r"(b) : "r"(addr));
}
__device__ __forceinline__ uint32_t smem_u32(const void* p) {
    uint32_t a;
    asm("{ .reg .u64 t; cvta.to.shared.u64 t, %1; cvt.u32.u64 %0, t; }"
        : "=r"(a) : "l"(p));
    return a;
}

#define MMA_F16_16x8x16(d, a0, a1, a2, a3, b0, b1) \
    asm volatile( \
        "mma.sync.aligned.m16n8k16.row.col.f32.f16.f16.f32 " \
        "{%0,%1,%2,%3}, {%4,%5,%6,%7}, {%8,%9}, {%0,%1,%2,%3};" \
        : "+f"((d)[0]), "+f"((d)[1]), "+f"((d)[2]), "+f"((d)[3]) \
        : "r"(a0), "r"(a1), "r"(a2), "r"(a3), "r"(b0), "r"(b1))

// smem row: 32 halfs = 16 half2-words, permuted within 8-word blocks:
//   s(w) = (w & 8) + 2*(w & 3) + ((w >> 2) & 1)
#define RSTRIDE 24

// ---------------- fused weight fp32 -> fp16 ----------------------------------
// W1: 131072 elems; rWih/rWhh/cWih/cWhh: 196608 each. Total 917504 = 229376 grp.
__global__ __launch_bounds__(256) void f2h5(
    const float* __restrict__ W1, const float* __restrict__ rWih,
    const float* __restrict__ rWhh, const float* __restrict__ cWih,
    const float* __restrict__ cWhh,
    __half* __restrict__ o1, __half* __restrict__ o2, __half* __restrict__ o3,
    __half* __restrict__ o4, __half* __restrict__ o5)
{
    int e = (blockIdx.x * 256 + threadIdx.x) * 4;
    const float* src;
    __half* dst;
    int off;
    if (e < 131072) { src = W1; dst = o1; off = e; }
    else {
        int e2 = e - 131072;
        int w = e2 / 196608;
        off = e2 - w * 196608;
        src = (w == 0) ? rWih : (w == 1) ? rWhh : (w == 2) ? cWih : cWhh;
        dst = (w == 0) ? o2 : (w == 1) ? o3 : (w == 2) ? o4 : o5;
    }
    float4 v = *(const float4*)(src + off);
    uint2 o;
    o.x = h2pack(v.x, v.y);
    o.y = h2pack(v.z, v.w);
    *(uint2*)&dst[off] = o;
}

// ---------------- fp16 mma.sync GEMM body (BM=64, BN=128, 3 CTA/SM) ----------
// C[m,n] = sum_k A[m,k]*B[n,k] + bias[n]
// A: MxK (fp32 if AH=0, fp16 if AH=1), B: NxK fp16, bias fp32.
// 256 threads, 8 warps as 2(M) x 4(N); warp tile 32x32; acc 32 regs.
template <int RELU, int OUTH, int AH>
__device__ __forceinline__ void gemm_body(
    const void* __restrict__ Av, const __half* __restrict__ B,
    const float* __restrict__ bias, void* __restrict__ Cv,
    int M, int N, int K, int bm, int bn)
{
    __shared__ uint32_t As[64 * RSTRIDE];
    __shared__ uint32_t Bs[128 * RSTRIDE];

    const int tid = threadIdx.x;
    const int wid = tid >> 5;
    const int lane = tid & 31;
    const int gr = lane >> 2;
    const int tg = lane & 3;

    const int wm = (wid & 1) * 32;
    const int wn = (wid >> 1) * 32;

    const int lr = tid >> 3;        // 0..31
    const int lf = tid & 7;         // 4-element k-group

    const float* Apf = (const float*)Av + (long)(bm + lr) * K + lf * 4;
    const __half* Aph = (const __half*)Av + (long)(bm + lr) * K + lf * 4;
    const __half* Bp = B + (long)(bn + lr) * K + lf * 4;
    const long strideR = (long)32 * K;

    const int il = lf & 3;
    const int sFirst = ((lf & 4) << 1) + (il & 1) * 4 + (il >> 1);

    const uint32_t aBase = smem_u32(As);
    const uint32_t bBase = smem_u32(Bs);

    float acc[2][4][4];
#pragma unroll
    for (int i = 0; i < 2; i++)
#pragma unroll
        for (int j = 0; j < 4; j++)
#pragma unroll
            for (int e = 0; e < 4; e++) acc[i][j][e] = 0.0f;

    float4 arf[2];
    uint2 arh[2], brh[4];
#pragma unroll
    for (int i = 0; i < 2; i++) {
        if (AH) arh[i] = *(const uint2*)(Aph + i * strideR);
        else    arf[i] = *(const float4*)(Apf + i * strideR);
    }
#pragma unroll
    for (int i = 0; i < 4; i++) brh[i] = *(const uint2*)(Bp + i * strideR);

    for (int k0 = 0; k0 < K; k0 += 32) {
        __syncthreads();
#pragma unroll
        for (int i = 0; i < 2; i++) {
            uint32_t* aw = (uint32_t*)As + (lr + i * 32) * RSTRIDE + sFirst;
            if (AH) { aw[0] = arh[i].x; aw[2] = arh[i].y; }
            else {
                aw[0] = h2pack(arf[i].x, arf[i].y);
                aw[2] = h2pack(arf[i].z, arf[i].w);
            }
        }
#pragma unroll
        for (int i = 0; i < 4; i++) {
            uint32_t* bw = (uint32_t*)Bs + (lr + i * 32) * RSTRIDE + sFirst;
            bw[0] = brh[i].x; bw[2] = brh[i].y;
        }
        __syncthreads();

        if (k0 + 32 < K) {
#pragma unroll
            for (int i = 0; i < 2; i++) {
                if (AH) arh[i] = *(const uint2*)(Aph + (k0 + 32) + i * strideR);
                else    arf[i] = *(const float4*)(Apf + (k0 + 32) + i * strideR);
            }
#pragma unroll
            for (int i = 0; i < 4; i++)
                brh[i] = *(const uint2*)(Bp + (k0 + 32) + i * strideR);
        }

#pragma unroll
        for (int kk = 0; kk < 2; kk++) {
            const uint32_t kwb = (uint32_t)(kk * 8 + 2 * tg) * 4u;
            uint32_t af[2][4];
            uint32_t bf[4][2];
#pragma unroll
            for (int i = 0; i < 2; i++) {
                const int r0 = wm + 16 * i + gr;
                lds64(af[i][0], af[i][2], aBase + (uint32_t)(r0 * RSTRIDE) * 4u + kwb);
                lds64(af[i][1], af[i][3], aBase + (uint32_t)((r0 + 8) * RSTRIDE) * 4u + kwb);
            }
#pragma unroll
            for (int j = 0; j < 4; j++) {
                const int n0 = wn + 8 * j + gr;
                lds64(bf[j][0], bf[j][1], bBase + (uint32_t)(n0 * RSTRIDE) * 4u + kwb);
            }
#pragma unroll
            for (int i = 0; i < 2; i++)
#pragma unroll
                for (int j = 0; j < 4; j++)
                    MMA_F16_16x8x16(acc[i][j], af[i][0], af[i][1], af[i][2], af[i][3],
                                    bf[j][0], bf[j][1]);
        }
    }

    // epilogue
#pragma unroll
    for (int j = 0; j < 4; j++) {
        const int col = bn + wn + 8 * j + 2 * tg;
        const float2 bb = *(const float2*)&bias[col];
#pragma unroll
        for (int i = 0; i < 2; i++) {
            const long r0 = (long)(bm + wm + 16 * i + gr);
            float2 v0, v1;
            v0.x = acc[i][j][0] + bb.x;
            v0.y = acc[i][j][1] + bb.y;
            v1.x = acc[i][j][2] + bb.x;
            v1.y = acc[i][j][3] + bb.y;
            if (RELU) {
                v0.x = fmaxf(v0.x, 0.0f); v0.y = fmaxf(v0.y, 0.0f);
                v1.x = fmaxf(v1.x, 0.0f); v1.y = fmaxf(v1.y, 0.0f);
            }
            if (OUTH) {
                __half* Ch = (__half*)Cv;
                *(uint32_t*)&Ch[r0 * N + col] = h2pack(v0.x, v0.y);
                *(uint32_t*)&Ch[(r0 + 8) * N + col] = h2pack(v1.x, v1.y);
            } else {
                float* Cf = (float*)Cv;
                *(float2*)&Cf[r0 * N + col] = v0;
                *(float2*)&Cf[(r0 + 8) * N + col] = v1;
            }
        }
    }
}

template <int RELU, int OUTH, int AH>
__global__ __launch_bounds__(256, 3) void gemm_mma(
    const void* __restrict__ Av, const __half* __restrict__ B,
    const float* __restrict__ bias, void* __restrict__ Cv,
    int M, int N, int K)
{
    gemm_body<RELU, OUTH, AH>(Av, B, bias, Cv, M, N, K,
                              blockIdx.y * 64, blockIdx.x * 128);
}

// dual GEMM: z=0 -> (A0,B0,bias0,C0), z=1 -> (A1,B1,bias1,C1). All fp16 A/out.
__global__ __launch_bounds__(256, 3) void gemm_mma_dual(
    const __half* __restrict__ A0, const __half* __restrict__ A1,
    const __half* __restrict__ B0, const __half* __restrict__ B1,
    const float* __restrict__ bias0, const float* __restrict__ bias1,
    __half* __restrict__ C0, __half* __restrict__ C1,
    int M, int N, int K)
{
    if (blockIdx.z == 0)
        gemm_body<0, 1, 1>(A0, B0, bias0, C0, M, N, K,
                           blockIdx.y * 64, blockIdx.x * 128);
    else
        gemm_body<0, 1, 1>(A1, B1, bias1, C1, M, N, K,
                           blockIdx.y * 64, blockIdx.x * 128);
}

// ---------------- GRU gate fusion --------------------------------------------
template <int HSH>
__global__ __launch_bounds__(256) void gru_gates(
    const __half* __restrict__ gi, const __half* __restrict__ gh,
    const void* __restrict__ hstate,
    __half* __restrict__ out0, float* __restrict__ out1)
{
    int idx = blockIdx.x * 256 + threadIdx.x;   // ROWS*64
    int row = idx >> 6;
    int c = (idx & 63) << 2;
    long g4 = (long)row * 192 + (c >> 2);
    long hbase = (long)row * H + c;

    const uint2* gi2 = (const uint2*)gi;
    const uint2* gh2 = (const uint2*)gh;

    uint2 iru = gi2[g4];
    uint2 izu = gi2[g4 + 64];
    uint2 inu = gi2[g4 + 128];
    uint2 hru = gh2[g4];
    uint2 hzu = gh2[g4 + 64];
    uint2 hnu = gh2[g4 + 128];

    float4 hv;
    if (HSH) {
        uint2 hu = *(const uint2*)((const __half*)hstate + hbase);
        float2 a = __half22float2(*(__half2*)&hu.x);
        float2 b = __half22float2(*(__half2*)&hu.y);
        hv = make_float4(a.x, a.y, b.x, b.y);
    } else {
        hv = *(const float4*)((const float*)hstate + hbase);
    }

    float2 irA = __half22float2(*(__half2*)&iru.x), irB = __half22float2(*(__half2*)&iru.y);
    float2 izA = __half22float2(*(__half2*)&izu.x), izB = __half22float2(*(__half2*)&izu.y);
    float2 inA = __half22float2(*(__half2*)&inu.x), inB = __half22float2(*(__half2*)&inu.y);
    float2 hrA = __half22float2(*(__half2*)&hru.x), hrB = __half22float2(*(__half2*)&hru.y);
    float2 hzA = __half22float2(*(__half2*)&hzu.x), hzB = __half22float2(*(__half2*)&hzu.y);
    float2 hnA = __half22float2(*(__half2*)&hnu.x), hnB = __half22float2(*(__half2*)&hnu.y);

    float4 o;
    { float r = sigm(irA.x + hrA.x), z = sigm(izA.x + hzA.x);
      float n = tanh_fast(inA.x + r * hnA.x); o.x = (1.0f - z) * n + z * hv.x; }
    { float r = sigm(irA.y + hrA.y), z = sigm(izA.y + hzA.y);
      float n = tanh_fast(inA.y + r * hnA.y); o.y = (1.0f - z) * n + z * hv.y; }
    { float r = sigm(irB.x + hrB.x), z = sigm(izB.x + hzB.x);
      float n = tanh_fast(inB.x + r * hnB.x); o.z = (1.0f - z) * n + z * hv.z; }
    { float r = sigm(irB.y + hrB.y), z = sigm(izB.y + hzB.y);
      float n = tanh_fast(inB.y + r * hnB.y); o.w = (1.0f - z) * n + z * hv.w; }

    uint2 oh;
    oh.x = h2pack(o.x, o.y);
    oh.y = h2pack(o.z, o.w);
    *(uint2*)&out0[hbase] = oh;
    if (out1) *(float4*)&out1[hbase] = o;
}

// ---------------- neighbor extraction ----------------------------------------
__global__ __launch_bounds__(256) void nb_kernel(
    const float* __restrict__ inp, float* __restrict__ nb, float* __restrict__ invn)
{
    int idx = blockIdx.x * 256 + threadIdx.x;
    int row = idx >> 5;
    int j = idx & 31;
    int i = row & 31;
    float v = 0.0f;
    if (j != i) {
        int k = (j > i) ? (j - 1) : j;
        v = inp[(long)row * IN_SHAPE + 260 + 8 * k];
    }
    float s = v;
#pragma unroll
    for (int o = 16; o > 0; o >>= 1) s += __shfl_xor_sync(0xffffffffu, s, o);
    nb[idx] = v;
    if (j == 0) invn[row] = 1.0f / s;
}

// ---------------- comm mix (fp16 h in, fp16 c out) ---------------------------
__global__ __launch_bounds__(256) void comm_mix(
    const __half* __restrict__ h, const float* __restrict__ nb,
    const float* __restrict__ invn, __half* __restrict__ out)
{
    __shared__ __half hs[32][256];
    __shared__ float At[32][36];
    __shared__ float sinv[32];

    int b = blockIdx.x;
    int tid = threadIdx.x;
    const __half* hb = h + (long)b * 32 * 256;

    // full tile: 32*256 halfs = 16384 B = 1024 uint4
#pragma unroll
    for (int t = tid; t < 1024; t += 256)
        ((uint4*)hs)[t] = ((const uint4*)hb)[t];
#pragma unroll
    for (int t = tid; t < 1024; t += 256) {
        int i = t >> 5;
        int j = t & 31;
        At[j][i] = nb[(long)(b * 32 + i) * 32 + j];
    }
    if (tid < 32) sinv[tid] = invn[b * 32 + tid];
    __syncthreads();

    float acc[32];
#pragma unroll
    for (int i = 0; i < 32; i++) acc[i] = 0.0f;

#pragma unroll 4
    for (int j = 0; j < 32; j++) {
        float hv = __half2float(hs[j][tid]);
#pragma unroll
        for (int i4 = 0; i4 < 32; i4 += 4) {
            float4 a = *(const float4*)&At[j][i4];
            acc[i4 + 0] += a.x * hv;
            acc[i4 + 1] += a.y * hv;
            acc[i4 + 2] += a.z * hv;
            acc[i4 + 3] += a.w * hv;
        }
    }
#pragma unroll
    for (int i = 0; i < 32; i++)
        out[(long)(b * 32 + i) * 256 + tid] = __float2half(acc[i] * sinv[i]);
}

// ---------------- q projection (fp16 h) ---------------------------------------
__global__ __launch_bounds__(256) void qproj(
    const __half* __restrict__ h, const float* __restrict__ W2,
    const float* __restrict__ b2, float* __restrict__ q)
{
    __shared__ float ws[16][260];
    __shared__ __half hsm[16][256];
    int tid = threadIdx.x;

#pragma unroll
    for (int t = tid; t < 1024; t += 256) {
        int n = t >> 6;
        int k4 = (t & 63) << 2;
        *(float4*)&ws[n][k4] = *(const float4*)&W2[n * 256 + k4];
    }
    const __half* hb = h + (long)blockIdx.x * 16 * 256;
#pragma unroll
    for (int t = tid; t < 2048; t += 256)
        ((uint32_t*)hsm)[t] = ((const uint32_t*)hb)[t];
    __syncthreads();

    int r = tid >> 4;
    int n = tid & 15;
    float s = 0.0f;
#pragma unroll 8
    for (int k = 0; k < 256; k += 2) {
        float2 hv = __half22float2(*(__half2*)&hsm[r][k]);
        s += hv.x * ws[n][k] + hv.y * ws[n][k + 1];
    }
    q[(long)(blockIdx.x * 16 + r) * 16 + n] = s + b2[n];
}

// ---------------- orchestration ----------------------------------------------
extern "C" void kernel_launch(void* const* d_in, const int* in_sizes, int n_in,
                              void* d_out, int out_size)
{
    (void)in_sizes; (void)n_in; (void)out_size;
    const float* inputs = (const float*)d_in[0];
    const float* hidden = (const float*)d_in[1];
    const float* W1     = (const float*)d_in[2];
    const float* b1     = (const float*)d_in[3];
    const float* rWih   = (const float*)d_in[4];
    const float* rWhh   = (const float*)d_in[5];
    const float* rbih   = (const float*)d_in[6];
    const float* rbhh   = (const float*)d_in[7];
    const float* cWih   = (const float*)d_in[8];
    const float* cWhh   = (const float*)d_in[9];
    const float* cbih   = (const float*)d_in[10];
    const float* cbhh   = (const float*)d_in[11];
    const float* W2     = (const float*)d_in[12];
    const float* b2     = (const float*)d_in[13];

    float* q_out = (float*)d_out;
    float* hrnn_out = q_out + (long)ROWS * NACT;

    __half *x, *gi, *gh, *h0, *h1, *c;
    float *nb, *invn;
    __half *hW1, *hrWih, *hrWhh, *hcWih, *hcWhh;
    cudaGetSymbolAddress((void**)&x, g_x);
    cudaGetSymbolAddress((void**)&gi, g_gi);
    cudaGetSymbolAddress((void**)&gh, g_gh);
    cudaGetSymbolAddress((void**)&h0, g_h0);
    cudaGetSymbolAddress((void**)&h1, g_h1);
    cudaGetSymbolAddress((void**)&c, g_c);
    cudaGetSymbolAddress((void**)&nb, g_nb);
    cudaGetSymbolAddress((void**)&invn, g_invn);
    cudaGetSymbolAddress((void**)&hW1, g_hW1);
    cudaGetSymbolAddress((void**)&hrWih, g_hrWih);
    cudaGetSymbolAddress((void**)&hrWhh, g_hrWhh);
    cudaGetSymbolAddress((void**)&hcWih, g_hcWih);
    cudaGetSymbolAddress((void**)&hcWhh, g_hcWhh);

    dim3 blk(256);

    // fused weight conversion: 917504 elems / 4 = 229376 groups / 256 = 896
    f2h5<<<896, blk>>>(W1, rWih, rWhh, cWih, cWhh, hW1, hrWih, hrWhh, hcWih, hcWhh);

    nb_kernel<<<ROWS * 32 / 256, blk>>>(inputs, nb, invn);

    dim3 gridW1(H / 128, ROWS / 64);
    dim3 gridG3(G3 / 128, ROWS / 64);
    dim3 gridDual(G3 / 128, ROWS / 64, 2);

    // x = relu(inputs @ W1^T + b1)   (A fp32, out fp16)
    gemm_mma<1, 1, 0><<<gridW1, blk>>>(inputs, hW1, b1, x, ROWS, H, IN_SHAPE);

    // h_rnn = GRU(x, hidden)
    gemm_mma<0, 1, 1><<<gridG3, blk>>>(x, hrWih, rbih, gi, ROWS, G3, H);
    gemm_mma<0, 1, 0><<<gridG3, blk>>>(hidden, hrWhh, rbhh, gh, ROWS, G3, H);
    gru_gates<0><<<ROWS * 64 / 256, blk>>>(gi, gh, hidden, h0, hrnn_out);

    __half* hc = h0;
    __half* hn = h1;
    for (int s = 0; s < 4; s++) {
        comm_mix<<<ROWS / NA, blk>>>(hc, nb, invn, c);
        gemm_mma_dual<<<gridDual, blk>>>(hc, c, hcWih, hcWhh, cbih, cbhh,
                                         gi, gh, ROWS, G3, H);
        gru_gates<1><<<ROWS * 64 / 256, blk>>>(gi, gh, c, hn, nullptr);
        __half* t2 = hc; hc = hn; hn = t2;
    }

    qproj<<<ROWS / 16, blk>>>(hc, W2, b2, q_out);
}

// round 17
// speedup vs baseline: 1.1220x; 1.1220x over previous
#include <cuda_runtime.h>
#include <cuda_fp16.h>
#include <cstdint>

#define ROWS 65536
#define H 256
#define IN_SHAPE 512
#define NA 32
#define NACT 16
#define G3 768   // 3*H

// ---------------- scratch (allocation-free: __device__ globals) -------------
__device__ __half g_x [(size_t)ROWS * H];
__device__ __half g_gi[(size_t)ROWS * G3];
__device__ __half g_gh[(size_t)ROWS * G3];
__device__ __half g_h0[(size_t)ROWS * H];
__device__ __half g_h1[(size_t)ROWS * H];
__device__ __half g_c [(size_t)ROWS * H];
__device__ float g_nb[(size_t)ROWS * NA];
__device__ float g_invn[(size_t)ROWS];
// fp16 weights (converted once per launch)
__device__ __half g_hW1  [H * IN_SHAPE];
__device__ __half g_hrWih[G3 * H];
__device__ __half g_hrWhh[G3 * H];
__device__ __half g_hcWih[G3 * H];
__device__ __half g_hcWhh[G3 * H];

__device__ __forceinline__ float sigm(float x) { return 1.0f / (1.0f + __expf(-x)); }
__device__ __forceinline__ float tanh_fast(float x) {
    return 2.0f / (1.0f + __expf(-2.0f * x)) - 1.0f;
}
__device__ __forceinline__ uint32_t h2pack(float lo, float hi) {
    __half2 h = __floats2half2_rn(lo, hi);
    return *(uint32_t*)&h;
}
__device__ __forceinline__ void lds64(uint32_t& a, uint32_t& b, uint32_t addr) {
    asm volatile("ld.shared.v2.b32 {%0,%1}, [%2];"
                 : "=r"(a), "=r"(b) : "r"(addr));
}
__device__ __forceinline__ uint32_t smem_u32(const void* p) {
    uint32_t a;
    asm("{ .reg .u64 t; cvta.to.shared.u64 t, %1; cvt.u32.u64 %0, t; }"
        : "=r"(a) : "l"(p));
    return a;
}

#define MMA_F16_16x8x16(d, a0, a1, a2, a3, b0, b1) \
    asm volatile( \
        "mma.sync.aligned.m16n8k16.row.col.f32.f16.f16.f32 " \
        "{%0,%1,%2,%3}, {%4,%5,%6,%7}, {%8,%9}, {%0,%1,%2,%3};" \
        : "+f"((d)[0]), "+f"((d)[1]), "+f"((d)[2]), "+f"((d)[3]) \
        : "r"(a0), "r"(a1), "r"(a2), "r"(a3), "r"(b0), "r"(b1))

// smem row: 32 halfs = 16 half2-words, permuted within 8-word blocks:
//   s(w) = (w & 8) + 2*(w & 3) + ((w >> 2) & 1)
#define RSTRIDE 24

// ---------------- fused weight fp32 -> fp16 ----------------------------------
__global__ __launch_bounds__(256) void f2h5(
    const float* __restrict__ W1, const float* __restrict__ rWih,
    const float* __restrict__ rWhh, const float* __restrict__ cWih,
    const float* __restrict__ cWhh,
    __half* __restrict__ o1, __half* __restrict__ o2, __half* __restrict__ o3,
    __half* __restrict__ o4, __half* __restrict__ o5)
{
    int e = (blockIdx.x * 256 + threadIdx.x) * 4;
    const float* src;
    __half* dst;
    int off;
    if (e < 131072) { src = W1; dst = o1; off = e; }
    else {
        int e2 = e - 131072;
        int w = e2 / 196608;
        off = e2 - w * 196608;
        src = (w == 0) ? rWih : (w == 1) ? rWhh : (w == 2) ? cWih : cWhh;
        dst = (w == 0) ? o2 : (w == 1) ? o3 : (w == 2) ? o4 : o5;
    }
    float4 v = *(const float4*)(src + off);
    uint2 o;
    o.x = h2pack(v.x, v.y);
    o.y = h2pack(v.z, v.w);
    *(uint2*)&dst[off] = o;
}

// ---------------- fp16 mma.sync GEMM body (BM=128, BN=128, 2 CTA/SM) ---------
// C[m,n] = sum_k A[m,k]*B[n,k] + bias[n]
// A: MxK (fp32 if AH=0, fp16 if AH=1), B: NxK fp16, bias fp32.
// 256 threads, 8 warps as 2(M) x 4(N); warp tile 64x32.
template <int RELU, int OUTH, int AH>
__device__ __forceinline__ void gemm_body(
    const void* __restrict__ Av, const __half* __restrict__ B,
    const float* __restrict__ bias, void* __restrict__ Cv,
    int N, int K, int bm, int bn)
{
    __shared__ uint32_t As[128 * RSTRIDE];
    __shared__ uint32_t Bs[128 * RSTRIDE];

    const int tid = threadIdx.x;
    const int wid = tid >> 5;
    const int lane = tid & 31;
    const int gr = lane >> 2;
    const int tg = lane & 3;

    const int wm = (wid & 1) * 64;
    const int wn = (wid >> 1) * 32;

    const int lr = tid >> 3;        // rows lr, lr+32, lr+64, lr+96
    const int lf = tid & 7;         // 4-element k-group

    const float* Apf = (const float*)Av + (long)(bm + lr) * K + lf * 4;
    const __half* Aph = (const __half*)Av + (long)(bm + lr) * K + lf * 4;
    const __half* Bp = B + (long)(bn + lr) * K + lf * 4;
    const long strideR = (long)32 * K;

    const int il = lf & 3;
    const int sFirst = ((lf & 4) << 1) + (il & 1) * 4 + (il >> 1);

    const uint32_t aBase = smem_u32(As);
    const uint32_t bBase = smem_u32(Bs);

    float acc[4][4][4];
#pragma unroll
    for (int i = 0; i < 4; i++)
#pragma unroll
        for (int j = 0; j < 4; j++)
#pragma unroll
            for (int e = 0; e < 4; e++) acc[i][j][e] = 0.0f;

    float4 arf[4];
    uint2 arh[4], brh[4];
#pragma unroll
    for (int i = 0; i < 4; i++) {
        if (AH) arh[i] = *(const uint2*)(Aph + i * strideR);
        else    arf[i] = *(const float4*)(Apf + i * strideR);
        brh[i] = *(const uint2*)(Bp + i * strideR);
    }

    for (int k0 = 0; k0 < K; k0 += 32) {
        __syncthreads();
#pragma unroll
        for (int i = 0; i < 4; i++) {
            const int r = lr + i * 32;
            uint32_t* aw = (uint32_t*)As + r * RSTRIDE + sFirst;
            uint32_t* bw = (uint32_t*)Bs + r * RSTRIDE + sFirst;
            if (AH) { aw[0] = arh[i].x; aw[2] = arh[i].y; }
            else {
                aw[0] = h2pack(arf[i].x, arf[i].y);
                aw[2] = h2pack(arf[i].z, arf[i].w);
            }
            bw[0] = brh[i].x; bw[2] = brh[i].y;
        }
        __syncthreads();

        if (k0 + 32 < K) {
#pragma unroll
            for (int i = 0; i < 4; i++) {
                if (AH) arh[i] = *(const uint2*)(Aph + (k0 + 32) + i * strideR);
                else    arf[i] = *(const float4*)(Apf + (k0 + 32) + i * strideR);
                brh[i] = *(const uint2*)(Bp + (k0 + 32) + i * strideR);
            }
        }

#pragma unroll
        for (int kk = 0; kk < 2; kk++) {
            const uint32_t kwb = (uint32_t)(kk * 8 + 2 * tg) * 4u;
            uint32_t af[4][4];
            uint32_t bf[4][2];
#pragma unroll
            for (int i = 0; i < 4; i++) {
                const int r0 = wm + 16 * i + gr;
                lds64(af[i][0], af[i][2], aBase + (uint32_t)(r0 * RSTRIDE) * 4u + kwb);
                lds64(af[i][1], af[i][3], aBase + (uint32_t)((r0 + 8) * RSTRIDE) * 4u + kwb);
            }
#pragma unroll
            for (int j = 0; j < 4; j++) {
                const int n0 = wn + 8 * j + gr;
                lds64(bf[j][0], bf[j][1], bBase + (uint32_t)(n0 * RSTRIDE) * 4u + kwb);
            }
#pragma unroll
            for (int i = 0; i < 4; i++)
#pragma unroll
                for (int j = 0; j < 4; j++)
                    MMA_F16_16x8x16(acc[i][j], af[i][0], af[i][1], af[i][2], af[i][3],
                                    bf[j][0], bf[j][1]);
        }
    }

    // epilogue
#pragma unroll
    for (int j = 0; j < 4; j++) {
        const int col = bn + wn + 8 * j + 2 * tg;
        const float2 bb = *(const float2*)&bias[col];
#pragma unroll
        for (int i = 0; i < 4; i++) {
            const long r0 = (long)(bm + wm + 16 * i + gr);
            float2 v0, v1;
            v0.x = acc[i][j][0] + bb.x;
            v0.y = acc[i][j][1] + bb.y;
            v1.x = acc[i][j][2] + bb.x;
            v1.y = acc[i][j][3] + bb.y;
            if (RELU) {
                v0.x = fmaxf(v0.x, 0.0f); v0.y = fmaxf(v0.y, 0.0f);
                v1.x = fmaxf(v1.x, 0.0f); v1.y = fmaxf(v1.y, 0.0f);
            }
            if (OUTH) {
                __half* Ch = (__half*)Cv;
                *(uint32_t*)&Ch[r0 * N + col] = h2pack(v0.x, v0.y);
                *(uint32_t*)&Ch[(r0 + 8) * N + col] = h2pack(v1.x, v1.y);
            } else {
                float* Cf = (float*)Cv;
                *(float2*)&Cf[r0 * N + col] = v0;
                *(float2*)&Cf[(r0 + 8) * N + col] = v1;
            }
        }
    }
}

template <int RELU, int OUTH, int AH>
__global__ __launch_bounds__(256) void gemm_mma(
    const void* __restrict__ Av, const __half* __restrict__ B,
    const float* __restrict__ bias, void* __restrict__ Cv,
    int N, int K)
{
    gemm_body<RELU, OUTH, AH>(Av, B, bias, Cv, N, K,
                              blockIdx.y * 128, blockIdx.x * 128);
}

// dual GEMM: z=0 -> (A0,B0,bias0,C0), z=1 -> (A1,B1,bias1,C1). fp16 A/out.
__global__ __launch_bounds__(256) void gemm_mma_dual(
    const __half* __restrict__ A0, const __half* __restrict__ A1,
    const __half* __restrict__ B0, const __half* __restrict__ B1,
    const float* __restrict__ bias0, const float* __restrict__ bias1,
    __half* __restrict__ C0, __half* __restrict__ C1,
    int N, int K)
{
    if (blockIdx.z == 0)
        gemm_body<0, 1, 1>(A0, B0, bias0, C0, N, K,
                           blockIdx.y * 128, blockIdx.x * 128);
    else
        gemm_body<0, 1, 1>(A1, B1, bias1, C1, N, K,
                           blockIdx.y * 128, blockIdx.x * 128);
}

// ---------------- GRU gate fusion --------------------------------------------
template <int HSH>
__global__ __launch_bounds__(256) void gru_gates(
    const __half* __restrict__ gi, const __half* __restrict__ gh,
    const void* __restrict__ hstate,
    __half* __restrict__ out0, float* __restrict__ out1)
{
    int idx = blockIdx.x * 256 + threadIdx.x;   // ROWS*64
    int row = idx >> 6;
    int c = (idx & 63) << 2;
    long g4 = (long)row * 192 + (c >> 2);
    long hbase = (long)row * H + c;

    const uint2* gi2 = (const uint2*)gi;
    const uint2* gh2 = (const uint2*)gh;

    uint2 iru = gi2[g4];
    uint2 izu = gi2[g4 + 64];
    uint2 inu = gi2[g4 + 128];
    uint2 hru = gh2[g4];
    uint2 hzu = gh2[g4 + 64];
    uint2 hnu = gh2[g4 + 128];

    float4 hv;
    if (HSH) {
        uint2 hu = *(const uint2*)((const __half*)hstate + hbase);
        float2 a = __half22float2(*(__half2*)&hu.x);
        float2 b = __half22float2(*(__half2*)&hu.y);
        hv = make_float4(a.x, a.y, b.x, b.y);
    } else {
        hv = *(const float4*)((const float*)hstate + hbase);
    }

    float2 irA = __half22float2(*(__half2*)&iru.x), irB = __half22float2(*(__half2*)&iru.y);
    float2 izA = __half22float2(*(__half2*)&izu.x), izB = __half22float2(*(__half2*)&izu.y);
    float2 inA = __half22float2(*(__half2*)&inu.x), inB = __half22float2(*(__half2*)&inu.y);
    float2 hrA = __half22float2(*(__half2*)&hru.x), hrB = __half22float2(*(__half2*)&hru.y);
    float2 hzA = __half22float2(*(__half2*)&hzu.x), hzB = __half22float2(*(__half2*)&hzu.y);
    float2 hnA = __half22float2(*(__half2*)&hnu.x), hnB = __half22float2(*(__half2*)&hnu.y);

    float4 o;
    { float r = sigm(irA.x + hrA.x), z = sigm(izA.x + hzA.x);
      float n = tanh_fast(inA.x + r * hnA.x); o.x = (1.0f - z) * n + z * hv.x; }
    { float r = sigm(irA.y + hrA.y), z = sigm(izA.y + hzA.y);
      float n = tanh_fast(inA.y + r * hnA.y); o.y = (1.0f - z) * n + z * hv.y; }
    { float r = sigm(irB.x + hrB.x), z = sigm(izB.x + hzB.x);
      float n = tanh_fast(inB.x + r * hnB.x); o.z = (1.0f - z) * n + z * hv.z; }
    { float r = sigm(irB.y + hrB.y), z = sigm(izB.y + hzB.y);
      float n = tanh_fast(inB.y + r * hnB.y); o.w = (1.0f - z) * n + z * hv.w; }

    uint2 oh;
    oh.x = h2pack(o.x, o.y);
    oh.y = h2pack(o.z, o.w);
    *(uint2*)&out0[hbase] = oh;
    if (out1) *(float4*)&out1[hbase] = o;
}

// ---------------- neighbor extraction ----------------------------------------
__global__ __launch_bounds__(256) void nb_kernel(
    const float* __restrict__ inp, float* __restrict__ nb, float* __restrict__ invn)
{
    int idx = blockIdx.x * 256 + threadIdx.x;
    int row = idx >> 5;
    int j = idx & 31;
    int i = row & 31;
    float v = 0.0f;
    if (j != i) {
        int k = (j > i) ? (j - 1) : j;
        v = inp[(long)row * IN_SHAPE + 260 + 8 * k];
    }
    float s = v;
#pragma unroll
    for (int o = 16; o > 0; o >>= 1) s += __shfl_xor_sync(0xffffffffu, s, o);
    nb[idx] = v;
    if (j == 0) invn[row] = 1.0f / s;
}

// ---------------- comm mix (fp16 h in, fp16 c out) ---------------------------
__global__ __launch_bounds__(256) void comm_mix(
    const __half* __restrict__ h, const float* __restrict__ nb,
    const float* __restrict__ invn, __half* __restrict__ out)
{
    __shared__ __half hs[32][256];
    __shared__ float At[32][36];
    __shared__ float sinv[32];

    int b = blockIdx.x;
    int tid = threadIdx.x;
    const __half* hb = h + (long)b * 32 * 256;

#pragma unroll
    for (int t = tid; t < 1024; t += 256)
        ((uint4*)hs)[t] = ((const uint4*)hb)[t];
#pragma unroll
    for (int t = tid; t < 1024; t += 256) {
        int i = t >> 5;
        int j = t & 31;
        At[j][i] = nb[(long)(b * 32 + i) * 32 + j];
    }
    if (tid < 32) sinv[tid] = invn[b * 32 + tid];
    __syncthreads();

    float acc[32];
#pragma unroll
    for (int i = 0; i < 32; i++) acc[i] = 0.0f;

#pragma unroll 4
    for (int j = 0; j < 32; j++) {
        float hv = __half2float(hs[j][tid]);
#pragma unroll
        for (int i4 = 0; i4 < 32; i4 += 4) {
            float4 a = *(const float4*)&At[j][i4];
            acc[i4 + 0] += a.x * hv;
            acc[i4 + 1] += a.y * hv;
            acc[i4 + 2] += a.z * hv;
            acc[i4 + 3] += a.w * hv;
        }
    }
#pragma unroll
    for (int i = 0; i < 32; i++)
        out[(long)(b * 32 + i) * 256 + tid] = __float2half(acc[i] * sinv[i]);
}

// ---------------- q projection (fp16 h) ---------------------------------------
__global__ __launch_bounds__(256) void qproj(
    const __half* __restrict__ h, const float* __restrict__ W2,
    const float* __restrict__ b2, float* __restrict__ q)
{
    __shared__ float ws[16][260];
    __shared__ __half hsm[16][256];
    int tid = threadIdx.x;

#pragma unroll
    for (int t = tid; t < 1024; t += 256) {
        int n = t >> 6;
        int k4 = (t & 63) << 2;
        *(float4*)&ws[n][k4] = *(const float4*)&W2[n * 256 + k4];
    }
    const __half* hb = h + (long)blockIdx.x * 16 * 256;
#pragma unroll
    for (int t = tid; t < 2048; t += 256)
        ((uint32_t*)hsm)[t] = ((const uint32_t*)hb)[t];
    __syncthreads();

    int r = tid >> 4;
    int n = tid & 15;
    float s = 0.0f;
#pragma unroll 8
    for (int k = 0; k < 256; k += 2) {
        float2 hv = __half22float2(*(__half2*)&hsm[r][k]);
        s += hv.x * ws[n][k] + hv.y * ws[n][k + 1];
    }
    q[(long)(blockIdx.x * 16 + r) * 16 + n] = s + b2[n];
}

// ---------------- orchestration ----------------------------------------------
extern "C" void kernel_launch(void* const* d_in, const int* in_sizes, int n_in,
                              void* d_out, int out_size)
{
    (void)in_sizes; (void)n_in; (void)out_size;
    const float* inputs = (const float*)d_in[0];
    const float* hidden = (const float*)d_in[1];
    const float* W1     = (const float*)d_in[2];
    const float* b1     = (const float*)d_in[3];
    const float* rWih   = (const float*)d_in[4];
    const float* rWhh   = (const float*)d_in[5];
    const float* rbih   = (const float*)d_in[6];
    const float* rbhh   = (const float*)d_in[7];
    const float* cWih   = (const float*)d_in[8];
    const float* cWhh   = (const float*)d_in[9];
    const float* cbih   = (const float*)d_in[10];
    const float* cbhh   = (const float*)d_in[11];
    const float* W2     = (const float*)d_in[12];
    const float* b2     = (const float*)d_in[13];

    float* q_out = (float*)d_out;
    float* hrnn_out = q_out + (long)ROWS * NACT;

    __half *x, *gi, *gh, *h0, *h1, *c;
    float *nb, *invn;
    __half *hW1, *hrWih, *hrWhh, *hcWih, *hcWhh;
    cudaGetSymbolAddress((void**)&x, g_x);
    cudaGetSymbolAddress((void**)&gi, g_gi);
    cudaGetSymbolAddress((void**)&gh, g_gh);
    cudaGetSymbolAddress((void**)&h0, g_h0);
    cudaGetSymbolAddress((void**)&h1, g_h1);
    cudaGetSymbolAddress((void**)&c, g_c);
    cudaGetSymbolAddress((void**)&nb, g_nb);
    cudaGetSymbolAddress((void**)&invn, g_invn);
    cudaGetSymbolAddress((void**)&hW1, g_hW1);
    cudaGetSymbolAddress((void**)&hrWih, g_hrWih);
    cudaGetSymbolAddress((void**)&hrWhh, g_hrWhh);
    cudaGetSymbolAddress((void**)&hcWih, g_hcWih);
    cudaGetSymbolAddress((void**)&hcWhh, g_hcWhh);

    dim3 blk(256);

    f2h5<<<896, blk>>>(W1, rWih, rWhh, cWih, cWhh, hW1, hrWih, hrWhh, hcWih, hcWhh);

    nb_kernel<<<ROWS * 32 / 256, blk>>>(inputs, nb, invn);

    dim3 gridW1(H / 128, ROWS / 128);
    dim3 gridG3(G3 / 128, ROWS / 128);
    dim3 gridDual(G3 / 128, ROWS / 128, 2);

    // x = relu(inputs @ W1^T + b1)   (A fp32, out fp16)
    gemm_mma<1, 1, 0><<<gridW1, blk>>>(inputs, hW1, b1, x, H, IN_SHAPE);

    // h_rnn = GRU(x, hidden)
    gemm_mma<0, 1, 1><<<gridG3, blk>>>(x, hrWih, rbih, gi, G3, H);
    gemm_mma<0, 1, 0><<<gridG3, blk>>>(hidden, hrWhh, rbhh, gh, G3, H);
    gru_gates<0><<<ROWS * 64 / 256, blk>>>(gi, gh, hidden, h0, hrnn_out);

    __half* hc = h0;
    __half* hn = h1;
    for (int s = 0; s < 4; s++) {
        comm_mix<<<ROWS / NA, blk>>>(hc, nb, invn, c);
        gemm_mma_dual<<<gridDual, blk>>>(hc, c, hcWih, hcWhh, cbih, cbhh,
                                         gi, gh, G3, H);
        gru_gates<1><<<ROWS * 64 / 256, blk>>>(gi, gh, c, hn, nullptr);
        __half* t2 = hc; hc = hn; hn = t2;
    }

    qproj<<<ROWS / 16, blk>>>(hc, W2, b2, q_out);
}